// round 13
// baseline (speedup 1.0000x reference)
#include <cuda_runtime.h>
#include <math.h>

#define B_ 32
#define S_ 2048
#define H_ 1024
#define NROWS (2 * B_ * S_)   // 131072
#define WARPS_PER_BLOCK 16
#define ROWS_PER_WARP 2
#define DOT_BLOCKS (NROWS / (WARPS_PER_BLOCK * ROWS_PER_WARP))   // 4096

// Scratch (allowed: __device__ globals, no allocation). Monotonic counter for
// the finalize gate survives graph replays (modulo test, no reset needed).
__device__ float              g_rewards[NROWS];
__device__ float              g_per_pair[B_];
__device__ int                g_accflag[B_];
__device__ unsigned long long g_fin_cnt;

__device__ __forceinline__ float warp_sum(float v) {
#pragma unroll
    for (int o = 16; o; o >>= 1) v += __shfl_xor_sync(0xffffffffu, v, o);
    return v;
}
__device__ __forceinline__ int warp_sum_i(int v) {
#pragma unroll
    for (int o = 16; o; o >>= 1) v += __shfl_xor_sync(0xffffffffu, v, o);
    return v;
}
__device__ __forceinline__ int warp_min_i(int v) {
#pragma unroll
    for (int o = 16; o; o >>= 1) v = min(v, __shfl_xor_sync(0xffffffffu, v, o));
    return v;
}

// ---------------------------------------------------------------------------
// Kernel 1: rewards[row] = dot(hidden[row, :], w)   (HBM-bound, 512 MB read)
// 16 warps/block x 2 rows/warp -> 4096 blocks: halves per-block fixed costs
// (w staging, BAR, launch/drain) vs the 8192-block variant; load pattern and
// per-warp MLP unchanged. Pinned at the LTS/HBM path ceiling (~6.76 TB/s).
// Early PDL trigger lets the secondary launch as soon as the last wave starts.
// ---------------------------------------------------------------------------
__global__ void __launch_bounds__(WARPS_PER_BLOCK * 32)
reward_dot_kernel(const float* __restrict__ hs, const float* __restrict__ w) {
    cudaTriggerProgrammaticLaunchCompletion();

    __shared__ float4 sw[H_ / 4];
    for (int i = threadIdx.x; i < H_ / 4; i += blockDim.x)
        sw[i] = reinterpret_cast<const float4*>(w)[i];
    __syncthreads();

    const int warp = threadIdx.x >> 5;
    const int lane = threadIdx.x & 31;
    const int row0 = (blockIdx.x * WARPS_PER_BLOCK + warp) * ROWS_PER_WARP;

    const float4* __restrict__ hp0 =
        reinterpret_cast<const float4*>(hs + (size_t)row0 * H_);
    const float4* __restrict__ hp1 =
        reinterpret_cast<const float4*>(hs + (size_t)(row0 + 1) * H_);

    float acc0 = 0.0f, acc1 = 0.0f;
#pragma unroll
    for (int i = 0; i < 8; i++) {
        float4 a  = __ldcs(&hp0[lane + i * 32]);   // streaming, no reuse
        float4 b  = __ldcs(&hp1[lane + i * 32]);
        float4 ww = sw[lane + i * 32];
        acc0 += a.x * ww.x + a.y * ww.y + a.z * ww.z + a.w * ww.w;
        acc1 += b.x * ww.x + b.y * ww.y + b.z * ww.z + b.w * ww.w;
    }
    acc0 = warp_sum(acc0);
    acc1 = warp_sum(acc1);
    if (lane == 0) {
        g_rewards[row0]     = acc0;
        g_rewards[row0 + 1] = acc1;
    }
}

// ---------------------------------------------------------------------------
// Kernel 2 (PDL secondary): per-pair scan + masked sums + fused finalize.
// Pre-sync phase (overlapped with the dot kernel): id scan from gmem.
// cudaGridDependencySynchronize() -> rewards complete and visible.
// Post-sync phase: batched smem staging of both reward rows (one burst of 64
// float4 loads block-wide = max MLP) + sums + last-block finalize.
// ---------------------------------------------------------------------------
__global__ void __launch_bounds__(1024)
pair_kernel(const int* __restrict__ ids, float* __restrict__ out) {
    const int b    = blockIdx.x;
    const int tid  = threadIdx.x;
    const int warp = tid >> 5;
    const int lane = tid & 31;

    __shared__ __align__(16) float s_rc[S_];
    __shared__ __align__(16) float s_rr[S_];
    __shared__ int   sc, sr, sd;
    __shared__ float sl[32], ss1[32], ss2[32];
    __shared__ int   sn[32];
    __shared__ bool  s_last;

    if (tid == 0) { sc = S_; sr = S_; sd = S_; }
    __syncthreads();

    // ---- pre-sync: id scan (independent of rewards; overlaps dot kernel) ---
    {
        // 1024 threads: tid<512 scan chosen row, tid>=512 scan rejected row.
        const bool is_c = tid < 512;
        const int  v    = is_c ? tid : tid - 512;   // int4 index 0..511
        const int4* __restrict__ idp = reinterpret_cast<const int4*>(
            ids + (size_t)(is_c ? b : B_ + b) * S_);
        const int4* __restrict__ idq = reinterpret_cast<const int4*>(
            ids + (size_t)(is_c ? B_ + b : b) * S_);
        int4 a4 = idp[v];
        int4 o4 = idq[v];
        const int s = v * 4;
        int pmin = S_, dmin = S_;
        if (a4.w == 0) pmin = s + 3;
        if (a4.z == 0) pmin = s + 2;
        if (a4.y == 0) pmin = s + 1;
        if (a4.x == 0) pmin = s + 0;
        if (a4.w != o4.w) dmin = s + 3;
        if (a4.z != o4.z) dmin = s + 2;
        if (a4.y != o4.y) dmin = s + 1;
        if (a4.x != o4.x) dmin = s + 0;
        pmin = warp_min_i(pmin);
        dmin = warp_min_i(dmin);
        if (lane == 0) {
            if (pmin < S_) atomicMin(is_c ? &sc : &sr, pmin);
            if (dmin < S_) atomicMin(&sd, dmin);
        }
    }

    // ---- wait for the dot kernel to complete (rewards visible) ----
    cudaGridDependencySynchronize();
    __syncthreads();

    // ---- stage both reward rows: 1024 threads x 1 float4 (L2-hot burst) ----
    {
        const float4* __restrict__ rc4 =
            reinterpret_cast<const float4*>(g_rewards + (size_t)b * S_);
        const float4* __restrict__ rr4 =
            reinterpret_cast<const float4*>(g_rewards + (size_t)(B_ + b) * S_);
        if (tid < 512) reinterpret_cast<float4*>(s_rc)[tid]       = rc4[tid];
        else           reinterpret_cast<float4*>(s_rr)[tid - 512] = rr4[tid - 512];
    }
    __syncthreads();

    const int  c_ind     = sc;
    const int  r_ind_pad = sr;
    const bool has_div   = sd < S_;
    const int  div_ind   = has_div ? sd : (S_ - 1);
    const int  r_ind     = has_div ? r_ind_pad : c_ind;
    const int  end_ind   = has_div ? max(c_ind, r_ind_pad) : S_;

    float lsum = 0.0f, csum = 0.0f, rsum = 0.0f;
    int   cnt_local = 0;
    for (int s = div_ind + tid; s < end_ind; s += 1024) {
        float rc = s_rc[s], rr = s_rr[s];
        float x  = rc - rr;
        // log_sigmoid(x) = min(x,0) - log(1 + exp(-|x|))
        lsum += fminf(x, 0.0f) - __logf(1.0f + __expf(-fabsf(x)));
        csum += __fdividef(1.0f, 1.0f + __expf(-rc));
        rsum += __fdividef(1.0f, 1.0f + __expf(-rr));
        cnt_local++;
    }

    float wl = warp_sum(lsum), wc = warp_sum(csum), wr = warp_sum(rsum);
    int   wn = warp_sum_i(cnt_local);
    if (lane == 0) { sl[warp] = wl; ss1[warp] = wc; ss2[warp] = wr; sn[warp] = wn; }
    __syncthreads();

    if (tid == 0) {
        float L = 0, C = 0, R = 0; int N = 0;
#pragma unroll
        for (int i = 0; i < 32; i++) { L += sl[i]; C += ss1[i]; R += ss2[i]; N += sn[i]; }
        float cnt = fmaxf((float)N, 1.0f);
        g_per_pair[b] = L / cnt;
        g_accflag[b]  = ((C - R) / cnt > 0.5f) ? 1 : 0;
        int ci = c_ind - 1; if (ci < 0) ci = 0; if (ci >= S_) ci = S_ - 1;
        int ri = r_ind - 1; if (ri < 0) ri = 0; if (ri >= S_) ri = S_ - 1;
        out[2 + b]      = s_rc[ci];   // chosen_mean_score
        out[2 + B_ + b] = s_rr[ri];   // rejected_mean_score
        __threadfence();
        unsigned long long pf = atomicAdd(&g_fin_cnt, 1ULL);
        s_last = (pf % B_ == (unsigned long long)(B_ - 1));
        if (s_last) __threadfence();   // acquire other pairs' scratch
    }
    __syncthreads();

    // Last block to finish: deterministic final reduction (fixed order)
    if (s_last && tid < 32) {
        float pp = g_per_pair[tid];
        int   af = g_accflag[tid];
        float ls = warp_sum(pp);
        int   ac = warp_sum_i(af);
        if (tid == 0) {
            out[0] = -ls;          // loss
            out[1] = (float)ac;    // acc
        }
    }
}

// ---------------------------------------------------------------------------
extern "C" void kernel_launch(void* const* d_in, const int* in_sizes, int n_in,
                              void* d_out, int out_size) {
    const int*   ids = (const int*)d_in[0];     // input_ids  (2B, S) int32
    const float* hs  = (const float*)d_in[1];   // hidden     (2B, S, H) f32
    const float* w   = (const float*)d_in[2];   // w          (H,) f32
    float* out = (float*)d_out;

    reward_dot_kernel<<<DOT_BLOCKS, WARPS_PER_BLOCK * 32>>>(hs, w);

    // PDL secondary: launches once the last primary wave has STARTED (early
    // trigger in the dot kernel); pre-sync id scan overlaps the drain;
    // cudaGridDependencySynchronize() gates the reward reads.
    cudaLaunchConfig_t cfg = {};
    cfg.gridDim  = dim3(B_);
    cfg.blockDim = dim3(1024);
    cudaLaunchAttribute attr[1];
    attr[0].id = cudaLaunchAttributeProgrammaticStreamSerialization;
    attr[0].val.programmaticStreamSerializationAllowed = 1;
    cfg.attrs    = attr;
    cfg.numAttrs = 1;
    cudaLaunchKernelEx(&cfg, pair_kernel, ids, out);
}

// round 14
// speedup vs baseline: 1.0050x; 1.0050x over previous
#include <cuda_runtime.h>
#include <math.h>

#define B_ 32
#define S_ 2048
#define H_ 1024
#define NROWS (2 * B_ * S_)   // 131072
#define WARPS_PER_BLOCK 8
#define ROWS_PER_WARP 2
#define DOT_BLOCKS (NROWS / (WARPS_PER_BLOCK * ROWS_PER_WARP))   // 8192

// Scratch (allowed: __device__ globals, no allocation). Monotonic counter for
// the finalize gate survives graph replays (modulo test, no reset needed).
__device__ float              g_rewards[NROWS];
__device__ float              g_per_pair[B_];
__device__ int                g_accflag[B_];
__device__ unsigned long long g_fin_cnt;

__device__ __forceinline__ float warp_sum(float v) {
#pragma unroll
    for (int o = 16; o; o >>= 1) v += __shfl_xor_sync(0xffffffffu, v, o);
    return v;
}
__device__ __forceinline__ int warp_sum_i(int v) {
#pragma unroll
    for (int o = 16; o; o >>= 1) v += __shfl_xor_sync(0xffffffffu, v, o);
    return v;
}
__device__ __forceinline__ int warp_min_i(int v) {
#pragma unroll
    for (int o = 16; o; o >>= 1) v = min(v, __shfl_xor_sync(0xffffffffu, v, o));
    return v;
}

// ---------------------------------------------------------------------------
// Kernel 1: rewards[row] = dot(hidden[row, :], w)   (HBM-bound, 512 MB read)
// TWO rows per warp, interleaved streaming loads, 256-thread blocks (the
// thrice-reproduced optimum). Pinned at the LTS/HBM path ceiling (~6.76 TB/s,
// 85% of spec). Early PDL trigger: the secondary launches as soon as the last
// wave STARTS; cudaGridDependencySynchronize in the secondary still provides
// the completion/visibility gate.
// ---------------------------------------------------------------------------
__global__ void __launch_bounds__(WARPS_PER_BLOCK * 32)
reward_dot_kernel(const float* __restrict__ hs, const float* __restrict__ w) {
    cudaTriggerProgrammaticLaunchCompletion();

    __shared__ float4 sw[H_ / 4];
    for (int i = threadIdx.x; i < H_ / 4; i += blockDim.x)
        sw[i] = reinterpret_cast<const float4*>(w)[i];
    __syncthreads();

    const int warp = threadIdx.x >> 5;
    const int lane = threadIdx.x & 31;
    const int row0 = (blockIdx.x * WARPS_PER_BLOCK + warp) * ROWS_PER_WARP;

    const float4* __restrict__ hp0 =
        reinterpret_cast<const float4*>(hs + (size_t)row0 * H_);
    const float4* __restrict__ hp1 =
        reinterpret_cast<const float4*>(hs + (size_t)(row0 + 1) * H_);

    float acc0 = 0.0f, acc1 = 0.0f;
#pragma unroll
    for (int i = 0; i < 8; i++) {
        float4 a  = __ldcs(&hp0[lane + i * 32]);   // streaming, no reuse
        float4 b  = __ldcs(&hp1[lane + i * 32]);
        float4 ww = sw[lane + i * 32];
        acc0 += a.x * ww.x + a.y * ww.y + a.z * ww.z + a.w * ww.w;
        acc1 += b.x * ww.x + b.y * ww.y + b.z * ww.z + b.w * ww.w;
    }
    acc0 = warp_sum(acc0);
    acc1 = warp_sum(acc1);
    if (lane == 0) {
        g_rewards[row0]     = acc0;
        g_rewards[row0 + 1] = acc1;
    }
}

// ---------------------------------------------------------------------------
// Kernel 2 (PDL secondary): per-pair scan + masked sums + fused finalize.
// Pre-sync phase (overlapped with the dot kernel): id scan from gmem.
// cudaGridDependencySynchronize() -> rewards complete and visible.
// Post-sync phase: batched smem staging of both reward rows (one burst of 64
// float4 loads block-wide = max MLP) + sums + last-block finalize.
// ---------------------------------------------------------------------------
__global__ void __launch_bounds__(1024)
pair_kernel(const int* __restrict__ ids, float* __restrict__ out) {
    const int b    = blockIdx.x;
    const int tid  = threadIdx.x;
    const int warp = tid >> 5;
    const int lane = tid & 31;

    __shared__ __align__(16) float s_rc[S_];
    __shared__ __align__(16) float s_rr[S_];
    __shared__ int   sc, sr, sd;
    __shared__ float sl[32], ss1[32], ss2[32];
    __shared__ int   sn[32];
    __shared__ bool  s_last;

    if (tid == 0) { sc = S_; sr = S_; sd = S_; }
    __syncthreads();

    // ---- pre-sync: id scan (independent of rewards; overlaps dot kernel) ---
    {
        // 1024 threads: tid<512 scan chosen row, tid>=512 scan rejected row.
        const bool is_c = tid < 512;
        const int  v    = is_c ? tid : tid - 512;   // int4 index 0..511
        const int4* __restrict__ idp = reinterpret_cast<const int4*>(
            ids + (size_t)(is_c ? b : B_ + b) * S_);
        const int4* __restrict__ idq = reinterpret_cast<const int4*>(
            ids + (size_t)(is_c ? B_ + b : b) * S_);
        int4 a4 = idp[v];
        int4 o4 = idq[v];
        const int s = v * 4;
        int pmin = S_, dmin = S_;
        if (a4.w == 0) pmin = s + 3;
        if (a4.z == 0) pmin = s + 2;
        if (a4.y == 0) pmin = s + 1;
        if (a4.x == 0) pmin = s + 0;
        if (a4.w != o4.w) dmin = s + 3;
        if (a4.z != o4.z) dmin = s + 2;
        if (a4.y != o4.y) dmin = s + 1;
        if (a4.x != o4.x) dmin = s + 0;
        pmin = warp_min_i(pmin);
        dmin = warp_min_i(dmin);
        if (lane == 0) {
            if (pmin < S_) atomicMin(is_c ? &sc : &sr, pmin);
            if (dmin < S_) atomicMin(&sd, dmin);
        }
    }

    // ---- wait for the dot kernel to complete (rewards visible) ----
    cudaGridDependencySynchronize();
    __syncthreads();

    // ---- stage both reward rows: 1024 threads x 1 float4 (L2-hot burst) ----
    {
        const float4* __restrict__ rc4 =
            reinterpret_cast<const float4*>(g_rewards + (size_t)b * S_);
        const float4* __restrict__ rr4 =
            reinterpret_cast<const float4*>(g_rewards + (size_t)(B_ + b) * S_);
        if (tid < 512) reinterpret_cast<float4*>(s_rc)[tid]       = rc4[tid];
        else           reinterpret_cast<float4*>(s_rr)[tid - 512] = rr4[tid - 512];
    }
    __syncthreads();

    const int  c_ind     = sc;
    const int  r_ind_pad = sr;
    const bool has_div   = sd < S_;
    const int  div_ind   = has_div ? sd : (S_ - 1);
    const int  r_ind     = has_div ? r_ind_pad : c_ind;
    const int  end_ind   = has_div ? max(c_ind, r_ind_pad) : S_;

    float lsum = 0.0f, csum = 0.0f, rsum = 0.0f;
    int   cnt_local = 0;
    for (int s = div_ind + tid; s < end_ind; s += 1024) {
        float rc = s_rc[s], rr = s_rr[s];
        float x  = rc - rr;
        // log_sigmoid(x) = min(x,0) - log(1 + exp(-|x|))
        lsum += fminf(x, 0.0f) - __logf(1.0f + __expf(-fabsf(x)));
        csum += __fdividef(1.0f, 1.0f + __expf(-rc));
        rsum += __fdividef(1.0f, 1.0f + __expf(-rr));
        cnt_local++;
    }

    float wl = warp_sum(lsum), wc = warp_sum(csum), wr = warp_sum(rsum);
    int   wn = warp_sum_i(cnt_local);
    if (lane == 0) { sl[warp] = wl; ss1[warp] = wc; ss2[warp] = wr; sn[warp] = wn; }
    __syncthreads();

    if (tid == 0) {
        float L = 0, C = 0, R = 0; int N = 0;
#pragma unroll
        for (int i = 0; i < 32; i++) { L += sl[i]; C += ss1[i]; R += ss2[i]; N += sn[i]; }
        float cnt = fmaxf((float)N, 1.0f);
        g_per_pair[b] = L / cnt;
        g_accflag[b]  = ((C - R) / cnt > 0.5f) ? 1 : 0;
        int ci = c_ind - 1; if (ci < 0) ci = 0; if (ci >= S_) ci = S_ - 1;
        int ri = r_ind - 1; if (ri < 0) ri = 0; if (ri >= S_) ri = S_ - 1;
        out[2 + b]      = s_rc[ci];   // chosen_mean_score
        out[2 + B_ + b] = s_rr[ri];   // rejected_mean_score
        __threadfence();
        unsigned long long pf = atomicAdd(&g_fin_cnt, 1ULL);
        s_last = (pf % B_ == (unsigned long long)(B_ - 1));
        if (s_last) __threadfence();   // acquire other pairs' scratch
    }
    __syncthreads();

    // Last block to finish: deterministic final reduction (fixed order)
    if (s_last && tid < 32) {
        float pp = g_per_pair[tid];
        int   af = g_accflag[tid];
        float ls = warp_sum(pp);
        int   ac = warp_sum_i(af);
        if (tid == 0) {
            out[0] = -ls;          // loss
            out[1] = (float)ac;    // acc
        }
    }
}

// ---------------------------------------------------------------------------
extern "C" void kernel_launch(void* const* d_in, const int* in_sizes, int n_in,
                              void* d_out, int out_size) {
    const int*   ids = (const int*)d_in[0];     // input_ids  (2B, S) int32
    const float* hs  = (const float*)d_in[1];   // hidden     (2B, S, H) f32
    const float* w   = (const float*)d_in[2];   // w          (H,) f32
    float* out = (float*)d_out;

    reward_dot_kernel<<<DOT_BLOCKS, WARPS_PER_BLOCK * 32>>>(hs, w);

    // PDL secondary: launches once the last primary wave has STARTED (early
    // trigger in the dot kernel); pre-sync id scan overlaps the drain;
    // cudaGridDependencySynchronize() gates the reward reads.
    cudaLaunchConfig_t cfg = {};
    cfg.gridDim  = dim3(B_);
    cfg.blockDim = dim3(1024);
    cudaLaunchAttribute attr[1];
    attr[0].id = cudaLaunchAttributeProgrammaticStreamSerialization;
    attr[0].val.programmaticStreamSerializationAllowed = 1;
    cfg.attrs    = attr;
    cfg.numAttrs = 1;
    cudaLaunchKernelEx(&cfg, pair_kernel, ids, out);
}

// round 15
// speedup vs baseline: 1.0054x; 1.0004x over previous
#include <cuda_runtime.h>
#include <math.h>

#define B_ 32
#define S_ 2048
#define H_ 1024
#define NROWS (2 * B_ * S_)   // 131072
#define WARPS_PER_BLOCK 8
#define ROWS_PER_WARP 2
#define DOT_BLOCKS (NROWS / (WARPS_PER_BLOCK * ROWS_PER_WARP))   // 8192

// Scratch (allowed: __device__ globals, no allocation). Monotonic counter for
// the finalize gate survives graph replays (modulo test, no reset needed).
__device__ float              g_rewards[NROWS];
__device__ float              g_per_pair[B_];
__device__ int                g_accflag[B_];
__device__ unsigned long long g_fin_cnt;

__device__ __forceinline__ float warp_sum(float v) {
#pragma unroll
    for (int o = 16; o; o >>= 1) v += __shfl_xor_sync(0xffffffffu, v, o);
    return v;
}
__device__ __forceinline__ int warp_sum_i(int v) {
#pragma unroll
    for (int o = 16; o; o >>= 1) v += __shfl_xor_sync(0xffffffffu, v, o);
    return v;
}
__device__ __forceinline__ int warp_min_i(int v) {
#pragma unroll
    for (int o = 16; o; o >>= 1) v = min(v, __shfl_xor_sync(0xffffffffu, v, o));
    return v;
}

// ---------------------------------------------------------------------------
// Kernel 1: rewards[row] = dot(hidden[row, :], w)   (HBM-bound, 512 MB read)
// TWO rows per warp, interleaved streaming loads, 256-thread blocks (the
// reproduced optimum). Pinned at the LTS/HBM path ceiling (~6.76 TB/s, 85%
// of spec). Early PDL trigger: the secondary launches as soon as the last
// wave STARTS; cudaGridDependencySynchronize in the secondary still provides
// the completion/visibility gate.
// ---------------------------------------------------------------------------
__global__ void __launch_bounds__(WARPS_PER_BLOCK * 32)
reward_dot_kernel(const float* __restrict__ hs, const float* __restrict__ w) {
    cudaTriggerProgrammaticLaunchCompletion();

    __shared__ float4 sw[H_ / 4];
    for (int i = threadIdx.x; i < H_ / 4; i += blockDim.x)
        sw[i] = reinterpret_cast<const float4*>(w)[i];
    __syncthreads();

    const int warp = threadIdx.x >> 5;
    const int lane = threadIdx.x & 31;
    const int row0 = (blockIdx.x * WARPS_PER_BLOCK + warp) * ROWS_PER_WARP;

    const float4* __restrict__ hp0 =
        reinterpret_cast<const float4*>(hs + (size_t)row0 * H_);
    const float4* __restrict__ hp1 =
        reinterpret_cast<const float4*>(hs + (size_t)(row0 + 1) * H_);

    float acc0 = 0.0f, acc1 = 0.0f;
#pragma unroll
    for (int i = 0; i < 8; i++) {
        float4 a  = __ldcs(&hp0[lane + i * 32]);   // streaming, no reuse
        float4 b  = __ldcs(&hp1[lane + i * 32]);
        float4 ww = sw[lane + i * 32];
        acc0 += a.x * ww.x + a.y * ww.y + a.z * ww.z + a.w * ww.w;
        acc1 += b.x * ww.x + b.y * ww.y + b.z * ww.z + b.w * ww.w;
    }
    acc0 = warp_sum(acc0);
    acc1 = warp_sum(acc1);
    if (lane == 0) {
        g_rewards[row0]     = acc0;
        g_rewards[row0 + 1] = acc1;
    }
}

// ---------------------------------------------------------------------------
// Kernel 2 (PDL secondary): per-pair scan + masked sums + fused finalize.
// Pre-sync phase (overlapped with the dot kernel): id scan from gmem.
// cudaGridDependencySynchronize() -> rewards complete and visible.
// Post-sync phase: batched smem staging of both reward rows (one burst of 64
// float4 loads block-wide = max MLP) + sums + last-block finalize.
// ---------------------------------------------------------------------------
__global__ void __launch_bounds__(1024)
pair_kernel(const int* __restrict__ ids, float* __restrict__ out) {
    const int b    = blockIdx.x;
    const int tid  = threadIdx.x;
    const int warp = tid >> 5;
    const int lane = tid & 31;

    __shared__ __align__(16) float s_rc[S_];
    __shared__ __align__(16) float s_rr[S_];
    __shared__ int   sc, sr, sd;
    __shared__ float sl[32], ss1[32], ss2[32];
    __shared__ int   sn[32];
    __shared__ bool  s_last;

    if (tid == 0) { sc = S_; sr = S_; sd = S_; }
    __syncthreads();

    // ---- pre-sync: id scan (independent of rewards; overlaps dot kernel) ---
    {
        // 1024 threads: tid<512 scan chosen row, tid>=512 scan rejected row.
        const bool is_c = tid < 512;
        const int  v    = is_c ? tid : tid - 512;   // int4 index 0..511
        const int4* __restrict__ idp = reinterpret_cast<const int4*>(
            ids + (size_t)(is_c ? b : B_ + b) * S_);
        const int4* __restrict__ idq = reinterpret_cast<const int4*>(
            ids + (size_t)(is_c ? B_ + b : b) * S_);
        int4 a4 = idp[v];
        int4 o4 = idq[v];
        const int s = v * 4;
        int pmin = S_, dmin = S_;
        if (a4.w == 0) pmin = s + 3;
        if (a4.z == 0) pmin = s + 2;
        if (a4.y == 0) pmin = s + 1;
        if (a4.x == 0) pmin = s + 0;
        if (a4.w != o4.w) dmin = s + 3;
        if (a4.z != o4.z) dmin = s + 2;
        if (a4.y != o4.y) dmin = s + 1;
        if (a4.x != o4.x) dmin = s + 0;
        pmin = warp_min_i(pmin);
        dmin = warp_min_i(dmin);
        if (lane == 0) {
            if (pmin < S_) atomicMin(is_c ? &sc : &sr, pmin);
            if (dmin < S_) atomicMin(&sd, dmin);
        }
    }

    // ---- wait for the dot kernel to complete (rewards visible) ----
    cudaGridDependencySynchronize();
    __syncthreads();

    // ---- stage both reward rows: 1024 threads x 1 float4 (L2-hot burst) ----
    {
        const float4* __restrict__ rc4 =
            reinterpret_cast<const float4*>(g_rewards + (size_t)b * S_);
        const float4* __restrict__ rr4 =
            reinterpret_cast<const float4*>(g_rewards + (size_t)(B_ + b) * S_);
        if (tid < 512) reinterpret_cast<float4*>(s_rc)[tid]       = rc4[tid];
        else           reinterpret_cast<float4*>(s_rr)[tid - 512] = rr4[tid - 512];
    }
    __syncthreads();

    const int  c_ind     = sc;
    const int  r_ind_pad = sr;
    const bool has_div   = sd < S_;
    const int  div_ind   = has_div ? sd : (S_ - 1);
    const int  r_ind     = has_div ? r_ind_pad : c_ind;
    const int  end_ind   = has_div ? max(c_ind, r_ind_pad) : S_;

    float lsum = 0.0f, csum = 0.0f, rsum = 0.0f;
    int   cnt_local = 0;
    for (int s = div_ind + tid; s < end_ind; s += 1024) {
        float rc = s_rc[s], rr = s_rr[s];
        float x  = rc - rr;
        // log_sigmoid(x) = min(x,0) - log(1 + exp(-|x|))
        lsum += fminf(x, 0.0f) - __logf(1.0f + __expf(-fabsf(x)));
        csum += __fdividef(1.0f, 1.0f + __expf(-rc));
        rsum += __fdividef(1.0f, 1.0f + __expf(-rr));
        cnt_local++;
    }

    float wl = warp_sum(lsum), wc = warp_sum(csum), wr = warp_sum(rsum);
    int   wn = warp_sum_i(cnt_local);
    if (lane == 0) { sl[warp] = wl; ss1[warp] = wc; ss2[warp] = wr; sn[warp] = wn; }
    __syncthreads();

    if (tid == 0) {
        float L = 0, C = 0, R = 0; int N = 0;
#pragma unroll
        for (int i = 0; i < 32; i++) { L += sl[i]; C += ss1[i]; R += ss2[i]; N += sn[i]; }
        float cnt = fmaxf((float)N, 1.0f);
        g_per_pair[b] = L / cnt;
        g_accflag[b]  = ((C - R) / cnt > 0.5f) ? 1 : 0;
        int ci = c_ind - 1; if (ci < 0) ci = 0; if (ci >= S_) ci = S_ - 1;
        int ri = r_ind - 1; if (ri < 0) ri = 0; if (ri >= S_) ri = S_ - 1;
        out[2 + b]      = s_rc[ci];   // chosen_mean_score
        out[2 + B_ + b] = s_rr[ri];   // rejected_mean_score
        __threadfence();
        unsigned long long pf = atomicAdd(&g_fin_cnt, 1ULL);
        s_last = (pf % B_ == (unsigned long long)(B_ - 1));
        if (s_last) __threadfence();   // acquire other pairs' scratch
    }
    __syncthreads();

    // Last block to finish: deterministic final reduction (fixed order)
    if (s_last && tid < 32) {
        float pp = g_per_pair[tid];
        int   af = g_accflag[tid];
        float ls = warp_sum(pp);
        int   ac = warp_sum_i(af);
        if (tid == 0) {
            out[0] = -ls;          // loss
            out[1] = (float)ac;    // acc
        }
    }
}

// ---------------------------------------------------------------------------
extern "C" void kernel_launch(void* const* d_in, const int* in_sizes, int n_in,
                              void* d_out, int out_size) {
    const int*   ids = (const int*)d_in[0];     // input_ids  (2B, S) int32
    const float* hs  = (const float*)d_in[1];   // hidden     (2B, S, H) f32
    const float* w   = (const float*)d_in[2];   // w          (H,) f32
    float* out = (float*)d_out;

    reward_dot_kernel<<<DOT_BLOCKS, WARPS_PER_BLOCK * 32>>>(hs, w);

    // PDL secondary: launches once the last primary wave has STARTED (early
    // trigger in the dot kernel); pre-sync id scan overlaps the drain;
    // cudaGridDependencySynchronize() gates the reward reads.
    cudaLaunchConfig_t cfg = {};
    cfg.gridDim  = dim3(B_);
    cfg.blockDim = dim3(1024);
    cudaLaunchAttribute attr[1];
    attr[0].id = cudaLaunchAttributeProgrammaticStreamSerialization;
    attr[0].val.programmaticStreamSerializationAllowed = 1;
    cfg.attrs    = attr;
    cfg.numAttrs = 1;
    cudaLaunchKernelEx(&cfg, pair_kernel, ids, out);
}

// round 16
// speedup vs baseline: 1.0314x; 1.0259x over previous
#include <cuda_runtime.h>
#include <math.h>

#define B_ 32
#define S_ 2048
#define H_ 1024
#define NROWS (2 * B_ * S_)   // 131072
#define WARPS_PER_BLOCK 8
#define ROWS_PER_WARP 2
#define DOT_BLOCKS (NROWS / (WARPS_PER_BLOCK * ROWS_PER_WARP))   // 8192

// Scratch (allowed: __device__ globals, no allocation). Monotonic counter for
// the finalize gate survives graph replays (modulo test, no reset needed).
__device__ float              g_rewards[NROWS];
__device__ float              g_per_pair[B_];
__device__ int                g_accflag[B_];
__device__ unsigned long long g_fin_cnt;

__device__ __forceinline__ float warp_sum(float v) {
#pragma unroll
    for (int o = 16; o; o >>= 1) v += __shfl_xor_sync(0xffffffffu, v, o);
    return v;
}
__device__ __forceinline__ int warp_sum_i(int v) {
#pragma unroll
    for (int o = 16; o; o >>= 1) v += __shfl_xor_sync(0xffffffffu, v, o);
    return v;
}
__device__ __forceinline__ int warp_min_i(int v) {
#pragma unroll
    for (int o = 16; o; o >>= 1) v = min(v, __shfl_xor_sync(0xffffffffu, v, o));
    return v;
}

// ---------------------------------------------------------------------------
// Kernel 1: rewards[row] = dot(hidden[row, :], w)   (HBM-bound, 512 MB read)
// TWO rows per warp, interleaved streaming loads, 256-thread blocks (the
// reproduced optimum). Pinned at the LTS/HBM path ceiling (~6.76 TB/s, 85%
// of spec). Early PDL trigger: the secondary launches as soon as the last
// wave STARTS; cudaGridDependencySynchronize in the secondary still provides
// the completion/visibility gate.
// ---------------------------------------------------------------------------
__global__ void __launch_bounds__(WARPS_PER_BLOCK * 32)
reward_dot_kernel(const float* __restrict__ hs, const float* __restrict__ w) {
    cudaTriggerProgrammaticLaunchCompletion();

    __shared__ float4 sw[H_ / 4];
    for (int i = threadIdx.x; i < H_ / 4; i += blockDim.x)
        sw[i] = reinterpret_cast<const float4*>(w)[i];
    __syncthreads();

    const int warp = threadIdx.x >> 5;
    const int lane = threadIdx.x & 31;
    const int row0 = (blockIdx.x * WARPS_PER_BLOCK + warp) * ROWS_PER_WARP;

    const float4* __restrict__ hp0 =
        reinterpret_cast<const float4*>(hs + (size_t)row0 * H_);
    const float4* __restrict__ hp1 =
        reinterpret_cast<const float4*>(hs + (size_t)(row0 + 1) * H_);

    float acc0 = 0.0f, acc1 = 0.0f;
#pragma unroll
    for (int i = 0; i < 8; i++) {
        float4 a  = __ldcs(&hp0[lane + i * 32]);   // streaming, no reuse
        float4 b  = __ldcs(&hp1[lane + i * 32]);
        float4 ww = sw[lane + i * 32];
        acc0 += a.x * ww.x + a.y * ww.y + a.z * ww.z + a.w * ww.w;
        acc1 += b.x * ww.x + b.y * ww.y + b.z * ww.z + b.w * ww.w;
    }
    acc0 = warp_sum(acc0);
    acc1 = warp_sum(acc1);
    if (lane == 0) {
        g_rewards[row0]     = acc0;
        g_rewards[row0 + 1] = acc1;
    }
}

// ---------------------------------------------------------------------------
// Kernel 2 (PDL secondary): per-pair scan + masked sums + fused finalize.
// Pre-sync phase (overlapped with the dot kernel): id scan from gmem.
// cudaGridDependencySynchronize() -> rewards complete and visible.
// Post-sync phase: REGISTER-RESIDENT float4 loads (thread t<512 loads rc4[t]
// + rr4[t] in one full-block burst -> same MLP as smem staging, but no smem
// store + barrier + LDS round on the critical path) + sums + gated finalize.
// ---------------------------------------------------------------------------
__global__ void __launch_bounds__(1024)
pair_kernel(const int* __restrict__ ids, float* __restrict__ out) {
    const int b    = blockIdx.x;
    const int tid  = threadIdx.x;
    const int warp = tid >> 5;
    const int lane = tid & 31;

    __shared__ int   sc, sr, sd;
    __shared__ float sl[16], ss1[16], ss2[16];
    __shared__ int   sn[16];
    __shared__ bool  s_last;

    if (tid == 0) { sc = S_; sr = S_; sd = S_; }
    __syncthreads();

    // ---- pre-sync: id scan (independent of rewards; overlaps dot kernel) ---
    {
        // 1024 threads: tid<512 scan chosen row, tid>=512 scan rejected row.
        const bool is_c = tid < 512;
        const int  v    = is_c ? tid : tid - 512;   // int4 index 0..511
        const int4* __restrict__ idp = reinterpret_cast<const int4*>(
            ids + (size_t)(is_c ? b : B_ + b) * S_);
        const int4* __restrict__ idq = reinterpret_cast<const int4*>(
            ids + (size_t)(is_c ? B_ + b : b) * S_);
        int4 a4 = idp[v];
        int4 o4 = idq[v];
        const int s = v * 4;
        int pmin = S_, dmin = S_;
        if (a4.w == 0) pmin = s + 3;
        if (a4.z == 0) pmin = s + 2;
        if (a4.y == 0) pmin = s + 1;
        if (a4.x == 0) pmin = s + 0;
        if (a4.w != o4.w) dmin = s + 3;
        if (a4.z != o4.z) dmin = s + 2;
        if (a4.y != o4.y) dmin = s + 1;
        if (a4.x != o4.x) dmin = s + 0;
        pmin = warp_min_i(pmin);
        dmin = warp_min_i(dmin);
        if (lane == 0) {
            if (pmin < S_) atomicMin(is_c ? &sc : &sr, pmin);
            if (dmin < S_) atomicMin(&sd, dmin);
        }
    }
    __syncthreads();   // indices final (still inside the overlap window)

    const int  c_ind     = sc;
    const int  r_ind_pad = sr;
    const bool has_div   = sd < S_;
    const int  div_ind   = has_div ? sd : (S_ - 1);
    const int  r_ind     = has_div ? r_ind_pad : c_ind;
    const int  end_ind   = has_div ? max(c_ind, r_ind_pad) : S_;

    // ---- wait for the dot kernel to complete (rewards visible) ----
    cudaGridDependencySynchronize();

    const float* __restrict__ rwc = g_rewards + (size_t)b * S_;
    const float* __restrict__ rwr = g_rewards + (size_t)(B_ + b) * S_;

    // ---- masked sums: one float4 pair per thread (tid<512), registers only --
    float lsum = 0.0f, csum = 0.0f, rsum = 0.0f;
    int   cnt_local = 0;
    if (tid < 512) {
        float4 c4 = __ldg(&reinterpret_cast<const float4*>(rwc)[tid]);
        float4 r4 = __ldg(&reinterpret_cast<const float4*>(rwr)[tid]);
        const int s0 = tid * 4;
        const float cs[4] = {c4.x, c4.y, c4.z, c4.w};
        const float rs[4] = {r4.x, r4.y, r4.z, r4.w};
#pragma unroll
        for (int k = 0; k < 4; k++) {
            const int s = s0 + k;
            if (s >= div_ind && s < end_ind) {
                float rc = cs[k], rr = rs[k];
                float x  = rc - rr;
                // log_sigmoid(x) = min(x,0) - log(1 + exp(-|x|))
                lsum += fminf(x, 0.0f) - __logf(1.0f + __expf(-fabsf(x)));
                csum += __fdividef(1.0f, 1.0f + __expf(-rc));
                rsum += __fdividef(1.0f, 1.0f + __expf(-rr));
                cnt_local++;
            }
        }
    }

    float wl = warp_sum(lsum), wc = warp_sum(csum), wr = warp_sum(rsum);
    int   wn = warp_sum_i(cnt_local);
    if (warp < 16 && lane == 0) { sl[warp] = wl; ss1[warp] = wc; ss2[warp] = wr; sn[warp] = wn; }
    __syncthreads();

    if (tid == 0) {
        float L = 0, C = 0, R = 0; int N = 0;
#pragma unroll
        for (int i = 0; i < 16; i++) { L += sl[i]; C += ss1[i]; R += ss2[i]; N += sn[i]; }
        float cnt = fmaxf((float)N, 1.0f);
        g_per_pair[b] = L / cnt;
        g_accflag[b]  = ((C - R) / cnt > 0.5f) ? 1 : 0;
        int ci = c_ind - 1; if (ci < 0) ci = 0; if (ci >= S_) ci = S_ - 1;
        int ri = r_ind - 1; if (ri < 0) ri = 0; if (ri >= S_) ri = S_ - 1;
        out[2 + b]      = __ldg(&rwc[ci]);   // chosen_mean_score
        out[2 + B_ + b] = __ldg(&rwr[ri]);   // rejected_mean_score
        __threadfence();
        unsigned long long pf = atomicAdd(&g_fin_cnt, 1ULL);
        s_last = (pf % B_ == (unsigned long long)(B_ - 1));
        if (s_last) __threadfence();   // acquire other pairs' scratch
    }
    __syncthreads();

    // Last block to finish: deterministic final reduction (fixed order)
    if (s_last && tid < 32) {
        float pp = g_per_pair[tid];
        int   af = g_accflag[tid];
        float ls = warp_sum(pp);
        int   ac = warp_sum_i(af);
        if (tid == 0) {
            out[0] = -ls;          // loss
            out[1] = (float)ac;    // acc
        }
    }
}

// ---------------------------------------------------------------------------
extern "C" void kernel_launch(void* const* d_in, const int* in_sizes, int n_in,
                              void* d_out, int out_size) {
    const int*   ids = (const int*)d_in[0];     // input_ids  (2B, S) int32
    const float* hs  = (const float*)d_in[1];   // hidden     (2B, S, H) f32
    const float* w   = (const float*)d_in[2];   // w          (H,) f32
    float* out = (float*)d_out;

    reward_dot_kernel<<<DOT_BLOCKS, WARPS_PER_BLOCK * 32>>>(hs, w);

    // PDL secondary: launches once the last primary wave has STARTED (early
    // trigger in the dot kernel); pre-sync id scan overlaps the drain;
    // cudaGridDependencySynchronize() gates the reward reads.
    cudaLaunchConfig_t cfg = {};
    cfg.gridDim  = dim3(B_);
    cfg.blockDim = dim3(1024);
    cudaLaunchAttribute attr[1];
    attr[0].id = cudaLaunchAttributeProgrammaticStreamSerialization;
    attr[0].val.programmaticStreamSerializationAllowed = 1;
    cfg.attrs    = attr;
    cfg.numAttrs = 1;
    cudaLaunchKernelEx(&cfg, pair_kernel, ids, out);
}